// round 14
// baseline (speedup 1.0000x reference)
#include <cuda_runtime.h>
#include <cuda_fp16.h>
#include <stdint.h>

// DayAdapter via fp16 mma.sync m16n8k16: y = softsign(x + xh@Eh + b),
// E = W - I. Fused streaming prep (x->fp16 + E transpose overlap in one
// launch). Main: BK=64, 3-stage (32KB/stage) mbarrier cp.async pipeline,
// 2 CTAs/SM, warp tile 64x32; epilogue identity term read from xh (fp16).

#define DIMK 512
#define TOK  1024
#define NB   64
#define NDAYS 24

#define CTA_M 128
#define CTA_N 128
#define BK    64
#define KSTEPS (DIMK / BK)       // 8
#define NTHREADS 256             // 8 warps: 2(m) x 4(n), warp tile 64x32
#define STAGES 3

#define SM_TILES 128             // mbarriers live in [0,128)
#define STG_BYTES 32768          // A 16KB | B 16KB, fp16 rows of 128B = 8 x 16B chunks
#define OFF_A 0
#define OFF_B 16384
#define SMEM_TOTAL (SM_TILES + STAGES * STG_BYTES)   // 98432

// prep grid split
#define XBLOCKS 16384            // 64*1024*512 / (8 floats/thread * 256 threads)
#define EBLOCKS 6144             // 24 days * 16*16 tiles of 32x32
#define PREP_BLOCKS (XBLOCKS + EBLOCKS)

__device__ __half g_xh[(size_t)NB * TOK * DIMK];       // fp16(x)
__device__ __half g_Eh[(size_t)NDAYS * DIMK * DIMK];   // fp16(E^T) [day][n][k]

// ---------------- helpers ----------------
__device__ __forceinline__ uint32_t smem_u32(const void* p) {
    return (uint32_t)__cvta_generic_to_shared(p);
}
// 128B rows, 8 chunks of 16B; conflict-free: ch ^= row&7
__device__ __forceinline__ uint32_t swz128(uint32_t row, uint32_t ch) {
    return row * 128u + ((ch ^ (row & 7u)) << 4);
}
__device__ __forceinline__ void ldsm_x4(uint32_t* r, uint32_t addr) {
    asm volatile("ldmatrix.sync.aligned.m8n8.x4.shared.b16 {%0,%1,%2,%3}, [%4];"
                 : "=r"(r[0]), "=r"(r[1]), "=r"(r[2]), "=r"(r[3]) : "r"(addr));
}
__device__ __forceinline__ void mma_f16(float* c, const uint32_t* a, uint32_t b0, uint32_t b1) {
    asm volatile(
        "mma.sync.aligned.m16n8k16.row.col.f32.f16.f16.f32 "
        "{%0,%1,%2,%3}, {%4,%5,%6,%7}, {%8,%9}, {%0,%1,%2,%3};"
        : "+f"(c[0]), "+f"(c[1]), "+f"(c[2]), "+f"(c[3])
        : "r"(a[0]), "r"(a[1]), "r"(a[2]), "r"(a[3]), "r"(b0), "r"(b1));
}
__device__ __forceinline__ void cp_async16(uint32_t dst, const void* src) {
    asm volatile("cp.async.cg.shared.global [%0], [%1], 16;" :: "r"(dst), "l"(src));
}
__device__ __forceinline__ void cp_mbar_arrive(uint32_t mbar) {
    asm volatile("cp.async.mbarrier.arrive.noinc.shared.b64 [%0];" :: "r"(mbar) : "memory");
}
__device__ __forceinline__ void mbar_init(uint32_t addr, uint32_t cnt) {
    asm volatile("mbarrier.init.shared.b64 [%0], %1;" :: "r"(addr), "r"(cnt) : "memory");
}
__device__ __forceinline__ void mbar_arrive(uint32_t addr) {
    asm volatile("mbarrier.arrive.shared.b64 _, [%0];" :: "r"(addr) : "memory");
}
__device__ __forceinline__ void mbar_wait(uint32_t addr, uint32_t parity) {
    asm volatile(
        "{\n\t.reg .pred P;\n"
        "W%=:\n\t"
        "mbarrier.try_wait.parity.acquire.cta.shared::cta.b64 P, [%0], %1, 0x989680;\n\t"
        "@!P bra W%=;\n\t}"
        :: "r"(addr), "r"(parity) : "memory");
}

// ---------------- fused prep: x-convert + E-transpose in one launch ----------------
__global__ void __launch_bounds__(256, 8) prep_fused(const float* __restrict__ x,
                                                     const float* __restrict__ W)
{
    __shared__ float t[32][33];
    const int bid = blockIdx.x;
    if (bid < XBLOCKS) {
        const size_t i = (size_t)bid * 256 + threadIdx.x;   // uint4-of-half index
        const float4 v0 = __ldg((const float4*)x + 2 * i);
        const float4 v1 = __ldg((const float4*)x + 2 * i + 1);
        __half2 h0 = __float22half2_rn(make_float2(v0.x, v0.y));
        __half2 h1 = __float22half2_rn(make_float2(v0.z, v0.w));
        __half2 h2 = __float22half2_rn(make_float2(v1.x, v1.y));
        __half2 h3 = __float22half2_rn(make_float2(v1.z, v1.w));
        uint4 o;
        o.x = *(uint32_t*)&h0; o.y = *(uint32_t*)&h1;
        o.z = *(uint32_t*)&h2; o.w = *(uint32_t*)&h3;
        ((uint4*)g_xh)[i] = o;
    } else {
        const int eb = bid - XBLOCKS;
        const int d  = eb >> 8;
        const int tl = eb & 255;
        const int k0 = (tl >> 4) * 32;
        const int n0 = (tl & 15) * 32;
        const int tx = threadIdx.x & 31;
        const int ty = threadIdx.x >> 5;
        const float* Wd = W + (size_t)d * DIMK * DIMK;
        #pragma unroll
        for (int i = ty; i < 32; i += 8)
            t[i][tx] = Wd[(size_t)(k0 + i) * DIMK + n0 + tx];
        __syncthreads();
        #pragma unroll
        for (int i = ty; i < 32; i += 8) {
            const int k = k0 + tx;
            const int n = n0 + i;
            float v = t[tx][i] - ((k == n) ? 1.0f : 0.0f);
            g_Eh[((size_t)d * DIMK + n) * DIMK + k] = __float2half_rn(v);
        }
    }
}

// ---------------- main ----------------
__global__ void __launch_bounds__(NTHREADS, 2)
day_adapter_f16(const float* __restrict__ x,
                const int*   __restrict__ day_w,
                const float* __restrict__ bias,
                float*       __restrict__ out)
{
    extern __shared__ char smem[];
    const uint32_t sb = smem_u32(smem);
    const int tid  = threadIdx.x;
    const int wid  = tid >> 5;
    const int lane = tid & 31;

    const int n0   = blockIdx.x * CTA_N;
    const int m0   = blockIdx.y * CTA_M;
    const int bidx = blockIdx.z;

    const uint32_t mb_full  = sb;        // full[i] at sb + i*8
    const uint32_t mb_empty = sb + 64;   // empty[i] at sb + 64 + i*8
    if (tid == 0) {
        #pragma unroll
        for (int i = 0; i < STAGES; i++) {
            mbar_init(mb_full  + i * 8, NTHREADS);
            mbar_init(mb_empty + i * 8, NTHREADS);
        }
    }

    // robust day_ids decode (int32 vs int64 buffer)
    int is64 = 1;
    #pragma unroll 8
    for (int i = 1; i < 64; i += 2)
        if (__ldg(day_w + i) != 0) is64 = 0;
    const int day = is64 ? __ldg(day_w + 2 * bidx) : __ldg(day_w + bidx);

    __syncthreads();   // mbarrier init visible before any arrivals

    // -------- stage loaders: thread t -> row=t>>1, chunks (t&1)*4 .. +3 --------
    const int lrow = tid >> 1;
    const int lc0  = (tid & 1) * 4;
    const __half* agp = g_xh + ((size_t)bidx * TOK + m0 + lrow) * DIMK + lc0 * 8;
    const __half* bgp = g_Eh + ((size_t)day  * DIMK + n0 + lrow) * DIMK + lc0 * 8;
    const uint32_t ls0 = swz128(lrow, lc0),     ls1 = swz128(lrow, lc0 + 1),
                   ls2 = swz128(lrow, lc0 + 2), ls3 = swz128(lrow, lc0 + 3);

    auto LOAD_STAGE = [&](uint32_t stg, int s) {
        const __half* asrc = agp + s * BK;
        const __half* bsrc = bgp + s * BK;
        cp_async16(stg + OFF_A + ls0, asrc);
        cp_async16(stg + OFF_A + ls1, asrc + 8);
        cp_async16(stg + OFF_A + ls2, asrc + 16);
        cp_async16(stg + OFF_A + ls3, asrc + 24);
        cp_async16(stg + OFF_B + ls0, bsrc);
        cp_async16(stg + OFF_B + ls1, bsrc + 8);
        cp_async16(stg + OFF_B + ls2, bsrc + 16);
        cp_async16(stg + OFF_B + ls3, bsrc + 24);
    };

    // -------- warp tile: 2(m) x 4(n), 64x32 --------
    const int mw = (wid >> 2) * 64;
    const int nw = (wid & 3) * 32;
    const int kswap = (wid & 1) * 2;         // odd warps traverse kg as 2,3,0,1

    float acc[4][4][4];
    #pragma unroll
    for (int i = 0; i < 4; i++)
        #pragma unroll
        for (int j = 0; j < 4; j++)
            #pragma unroll
            for (int q = 0; q < 4; q++) acc[i][j][q] = 0.0f;

    // ldmatrix lane addressing (fp16, 128B rows)
    const int a_row = mw + (lane & 15);                       // + mt*16
    const int a_ch  = lane >> 4;                              // + 2*kk
    const int b_row = nw + (lane & 7) + ((lane >> 4) << 3);   // + np*16
    const int b_ch  = (lane >> 3) & 1;                        // + 2*kk

    // -------- prolog: fill slots 0..1 --------
    LOAD_STAGE(sb + SM_TILES + 0 * STG_BYTES, 0);
    cp_mbar_arrive(mb_full + 0 * 8);
    LOAD_STAGE(sb + SM_TILES + 1 * STG_BYTES, 1);
    cp_mbar_arrive(mb_full + 1 * 8);

    int slotC = 0;
    int slotP = STAGES - 1;
    uint32_t phF = 0, phE = 0;

    // -------- main loop: mbarrier-paced, no CTA barrier --------
    #pragma unroll 1
    for (int s = 0; s < KSTEPS; s++) {
        const uint32_t stg  = sb + SM_TILES + slotC * STG_BYTES;
        const uint32_t stgA = stg + OFF_A;
        const uint32_t stgB = stg + OFF_B;

        mbar_wait(mb_full + slotC * 8, (phF >> slotC) & 1);
        phF ^= 1u << slotC;

        // fragment double buffers; preload first kk (= kswap)
        uint32_t bf[2][8];
        uint32_t af[2][4];
        ldsm_x4(bf[0] + 0, stgB + swz128(b_row,      2 * kswap + b_ch));
        ldsm_x4(bf[0] + 4, stgB + swz128(b_row + 16, 2 * kswap + b_ch));
        ldsm_x4(af[0],     stgA + swz128(a_row,      2 * kswap + a_ch));

        // producer: refill slotP for stage s+2
        if (s + STAGES - 1 < KSTEPS) {
            if (s > 0) {
                mbar_wait(mb_empty + slotP * 8, (phE >> slotP) & 1);
                phE ^= 1u << slotP;
            }
            LOAD_STAGE(sb + SM_TILES + slotP * STG_BYTES, s + STAGES - 1);
            cp_mbar_arrive(mb_full + slotP * 8);
        }

        int ab = 0;
        #pragma unroll
        for (int kg = 0; kg < 4; kg++) {
            const int cur = kg & 1;
            const int kk  = kg ^ kswap;
            const int kkn = (kg + 1) ^ kswap;
            if (kg < 3) {
                ldsm_x4(bf[cur ^ 1] + 0, stgB + swz128(b_row,      2 * kkn + b_ch));
                ldsm_x4(bf[cur ^ 1] + 4, stgB + swz128(b_row + 16, 2 * kkn + b_ch));
            }
            #pragma unroll
            for (int mt = 0; mt < 4; mt++) {
                if (mt < 3)
                    ldsm_x4(af[ab ^ 1], stgA + swz128(a_row + (mt + 1) * 16, 2 * kk + a_ch));
                else if (kg < 3)
                    ldsm_x4(af[ab ^ 1], stgA + swz128(a_row, 2 * kkn + a_ch));
                #pragma unroll
                for (int nt = 0; nt < 4; nt++)
                    mma_f16(acc[mt][nt], af[ab],
                            bf[cur][(nt >> 1) * 4 + (nt & 1) * 2],
                            bf[cur][(nt >> 1) * 4 + (nt & 1) * 2 + 1]);
                ab ^= 1;
            }
        }

        mbar_arrive(mb_empty + slotC * 8);

        slotC = (slotC == STAGES - 1) ? 0 : slotC + 1;
        slotP = (slotP == STAGES - 1) ? 0 : slotP + 1;
    }

    // -------- epilogue: y = xh + acc + bias; softsign --------
    const int r  = lane >> 2;
    const int cq = (lane & 3) * 2;
    const __half* xhp = g_xh + (size_t)bidx * TOK * DIMK;
    const float* bp  = bias + (size_t)day * DIMK;

    #pragma unroll
    for (int nt = 0; nt < 4; nt++) {
        const int n = n0 + nw + nt * 8 + cq;
        const float2 bb = *(const float2*)(bp + n);
        #pragma unroll
        for (int mt = 0; mt < 4; mt++) {
            const int m = m0 + mw + mt * 16 + r;
            const __half2 hx0 = *(const __half2*)(xhp + (size_t)m * DIMK + n);
            const __half2 hx1 = *(const __half2*)(xhp + (size_t)(m + 8) * DIMK + n);
            const float2 x0 = __half22float2(hx0);
            const float2 x1 = __half22float2(hx1);
            float y0 = acc[mt][nt][0] + x0.x + bb.x;
            float y1 = acc[mt][nt][1] + x0.y + bb.y;
            float y2 = acc[mt][nt][2] + x1.x + bb.x;
            float y3 = acc[mt][nt][3] + x1.y + bb.y;
            float2 o0, o1;
            o0.x = __fdividef(y0, 1.0f + fabsf(y0));
            o0.y = __fdividef(y1, 1.0f + fabsf(y1));
            o1.x = __fdividef(y2, 1.0f + fabsf(y2));
            o1.y = __fdividef(y3, 1.0f + fabsf(y3));
            *(float2*)(out + (size_t)bidx * TOK * DIMK + (size_t)m * DIMK + n)       = o0;
            *(float2*)(out + (size_t)bidx * TOK * DIMK + (size_t)(m + 8) * DIMK + n) = o1;
        }
    }
}

// ---------------- launch ----------------
extern "C" void kernel_launch(void* const* d_in, const int* in_sizes, int n_in,
                              void* d_out, int out_size)
{
    const float* x   = (const float*)d_in[0];
    const int*   day = (const int*)  d_in[1];
    const float* W   = (const float*)d_in[2];
    const float* b   = (const float*)d_in[3];
    float*       out = (float*)d_out;

    cudaFuncSetAttribute(day_adapter_f16,
                         cudaFuncAttributeMaxDynamicSharedMemorySize, SMEM_TOTAL);

    prep_fused<<<PREP_BLOCKS, 256>>>(x, W);

    dim3 grid(DIMK / CTA_N, TOK / CTA_M, NB);   // (4, 8, 64) = 2048 CTAs
    day_adapter_f16<<<grid, NTHREADS, SMEM_TOTAL>>>(x, day, b, out);
}

// round 15
// speedup vs baseline: 1.0682x; 1.0682x over previous
#include <cuda_runtime.h>
#include <cuda_fp16.h>
#include <stdint.h>

// DayAdapter via fp16 mma.sync m16n8k16: y = softsign(x + xh@Eh + b),
// E = W - I. Fused streaming prep (x->fp16 + E transpose in one launch).
// Main: BK=32, 5-stage (16KB/stage) mbarrier cp.async pipeline, 2 CTAs/SM,
// warp tile 64x32; epilogue identity term read from xh (fp16).

#define DIMK 512
#define TOK  1024
#define NB   64
#define NDAYS 24

#define CTA_M 128
#define CTA_N 128
#define BK    32
#define KSTEPS (DIMK / BK)       // 16
#define NTHREADS 256             // 8 warps: 2(m) x 4(n), warp tile 64x32
#define STAGES 5

#define SM_TILES 128             // mbarriers live in [0,128)
#define STG_BYTES 16384          // A 8KB | B 8KB, fp16 rows of 64B = 4 x 16B chunks
#define OFF_A 0
#define OFF_B 8192
#define SMEM_TOTAL (SM_TILES + STAGES * STG_BYTES)   // 82048

// prep grid split
#define XBLOCKS 16384            // 64*1024*512 / (8 floats/thread * 256 threads)
#define EBLOCKS 6144             // 24 days * 16*16 tiles of 32x32
#define PREP_BLOCKS (XBLOCKS + EBLOCKS)

__device__ __half g_xh[(size_t)NB * TOK * DIMK];       // fp16(x)
__device__ __half g_Eh[(size_t)NDAYS * DIMK * DIMK];   // fp16(E^T) [day][n][k]

// ---------------- helpers ----------------
__device__ __forceinline__ uint32_t smem_u32(const void* p) {
    return (uint32_t)__cvta_generic_to_shared(p);
}
// 64B rows, 4 chunks of 16B; conflict-free: ch ^= (row>>1)&3
__device__ __forceinline__ uint32_t swz64(uint32_t row, uint32_t ch) {
    return row * 64u + ((ch ^ ((row >> 1) & 3u)) << 4);
}
__device__ __forceinline__ void ldsm_x4(uint32_t* r, uint32_t addr) {
    asm volatile("ldmatrix.sync.aligned.m8n8.x4.shared.b16 {%0,%1,%2,%3}, [%4];"
                 : "=r"(r[0]), "=r"(r[1]), "=r"(r[2]), "=r"(r[3]) : "r"(addr));
}
__device__ __forceinline__ void mma_f16(float* c, const uint32_t* a, uint32_t b0, uint32_t b1) {
    asm volatile(
        "mma.sync.aligned.m16n8k16.row.col.f32.f16.f16.f32 "
        "{%0,%1,%2,%3}, {%4,%5,%6,%7}, {%8,%9}, {%0,%1,%2,%3};"
        : "+f"(c[0]), "+f"(c[1]), "+f"(c[2]), "+f"(c[3])
        : "r"(a[0]), "r"(a[1]), "r"(a[2]), "r"(a[3]), "r"(b0), "r"(b1));
}
__device__ __forceinline__ void cp_async16(uint32_t dst, const void* src) {
    asm volatile("cp.async.cg.shared.global [%0], [%1], 16;" :: "r"(dst), "l"(src));
}
__device__ __forceinline__ void cp_mbar_arrive(uint32_t mbar) {
    asm volatile("cp.async.mbarrier.arrive.noinc.shared.b64 [%0];" :: "r"(mbar) : "memory");
}
__device__ __forceinline__ void mbar_init(uint32_t addr, uint32_t cnt) {
    asm volatile("mbarrier.init.shared.b64 [%0], %1;" :: "r"(addr), "r"(cnt) : "memory");
}
__device__ __forceinline__ void mbar_arrive(uint32_t addr) {
    asm volatile("mbarrier.arrive.shared.b64 _, [%0];" :: "r"(addr) : "memory");
}
__device__ __forceinline__ void mbar_wait(uint32_t addr, uint32_t parity) {
    asm volatile(
        "{\n\t.reg .pred P;\n"
        "W%=:\n\t"
        "mbarrier.try_wait.parity.acquire.cta.shared::cta.b64 P, [%0], %1, 0x989680;\n\t"
        "@!P bra W%=;\n\t}"
        :: "r"(addr), "r"(parity) : "memory");
}

// ---------------- fused prep: x-convert + E-transpose in one launch ----------------
__global__ void __launch_bounds__(256, 8) prep_fused(const float* __restrict__ x,
                                                     const float* __restrict__ W)
{
    __shared__ float t[32][33];
    const int bid = blockIdx.x;
    if (bid < XBLOCKS) {
        const size_t i = (size_t)bid * 256 + threadIdx.x;   // uint4-of-half index
        const float4 v0 = __ldg((const float4*)x + 2 * i);
        const float4 v1 = __ldg((const float4*)x + 2 * i + 1);
        __half2 h0 = __float22half2_rn(make_float2(v0.x, v0.y));
        __half2 h1 = __float22half2_rn(make_float2(v0.z, v0.w));
        __half2 h2 = __float22half2_rn(make_float2(v1.x, v1.y));
        __half2 h3 = __float22half2_rn(make_float2(v1.z, v1.w));
        uint4 o;
        o.x = *(uint32_t*)&h0; o.y = *(uint32_t*)&h1;
        o.z = *(uint32_t*)&h2; o.w = *(uint32_t*)&h3;
        ((uint4*)g_xh)[i] = o;
    } else {
        const int eb = bid - XBLOCKS;
        const int d  = eb >> 8;
        const int tl = eb & 255;
        const int k0 = (tl >> 4) * 32;
        const int n0 = (tl & 15) * 32;
        const int tx = threadIdx.x & 31;
        const int ty = threadIdx.x >> 5;
        const float* Wd = W + (size_t)d * DIMK * DIMK;
        #pragma unroll
        for (int i = ty; i < 32; i += 8)
            t[i][tx] = Wd[(size_t)(k0 + i) * DIMK + n0 + tx];
        __syncthreads();
        #pragma unroll
        for (int i = ty; i < 32; i += 8) {
            const int k = k0 + tx;
            const int n = n0 + i;
            float v = t[tx][i] - ((k == n) ? 1.0f : 0.0f);
            g_Eh[((size_t)d * DIMK + n) * DIMK + k] = __float2half_rn(v);
        }
    }
}

// ---------------- main ----------------
__global__ void __launch_bounds__(NTHREADS, 2)
day_adapter_f16(const float* __restrict__ x,
                const int*   __restrict__ day_w,
                const float* __restrict__ bias,
                float*       __restrict__ out)
{
    extern __shared__ char smem[];
    const uint32_t sb = smem_u32(smem);
    const int tid  = threadIdx.x;
    const int wid  = tid >> 5;
    const int lane = tid & 31;

    const int n0   = blockIdx.x * CTA_N;
    const int m0   = blockIdx.y * CTA_M;
    const int bidx = blockIdx.z;

    const uint32_t mb_full  = sb;        // full[i] at sb + i*8
    const uint32_t mb_empty = sb + 64;   // empty[i] at sb + 64 + i*8
    if (tid == 0) {
        #pragma unroll
        for (int i = 0; i < STAGES; i++) {
            mbar_init(mb_full  + i * 8, NTHREADS);
            mbar_init(mb_empty + i * 8, NTHREADS);
        }
    }

    // robust day_ids decode (int32 vs int64 buffer)
    int is64 = 1;
    #pragma unroll 8
    for (int i = 1; i < 64; i += 2)
        if (__ldg(day_w + i) != 0) is64 = 0;
    const int day = is64 ? __ldg(day_w + 2 * bidx) : __ldg(day_w + bidx);

    __syncthreads();   // mbarrier init visible before any arrivals

    // -------- stage loaders: thread t -> row=t>>1, chunks (t&1)*2, +1 --------
    const int lrow = tid >> 1;
    const int lc0  = (tid & 1) * 2;
    const __half* agp = g_xh + ((size_t)bidx * TOK + m0 + lrow) * DIMK + lc0 * 8;
    const __half* bgp = g_Eh + ((size_t)day  * DIMK + n0 + lrow) * DIMK + lc0 * 8;
    const uint32_t lso0 = swz64(lrow, lc0), lso1 = swz64(lrow, lc0 + 1);

    auto LOAD_STAGE = [&](uint32_t stg, int s) {
        const __half* asrc = agp + s * BK;
        const __half* bsrc = bgp + s * BK;
        cp_async16(stg + OFF_A + lso0, asrc);
        cp_async16(stg + OFF_A + lso1, asrc + 8);
        cp_async16(stg + OFF_B + lso0, bsrc);
        cp_async16(stg + OFF_B + lso1, bsrc + 8);
    };

    // -------- warp tile: 2(m) x 4(n), 64x32 --------
    const int mw = (wid >> 2) * 64;
    const int nw = (wid & 3) * 32;
    const int kswap = wid & 1;               // odd warps traverse kg as 1,0

    float acc[4][4][4];
    #pragma unroll
    for (int i = 0; i < 4; i++)
        #pragma unroll
        for (int j = 0; j < 4; j++)
            #pragma unroll
            for (int q = 0; q < 4; q++) acc[i][j][q] = 0.0f;

    // ldmatrix lane addressing (fp16, 64B rows)
    const int a_row = mw + (lane & 15);                       // + mt*16
    const int a_ch  = lane >> 4;                              // + 2*kg
    const int b_row = nw + (lane & 7) + ((lane >> 4) << 3);   // + np*16
    const int b_ch  = (lane >> 3) & 1;                        // + 2*kg

    // -------- prolog: fill slots 0..3 --------
    #pragma unroll
    for (int i = 0; i < STAGES - 1; i++) {
        LOAD_STAGE(sb + SM_TILES + i * STG_BYTES, i);
        cp_mbar_arrive(mb_full + i * 8);
    }

    int slotC = 0;
    int slotP = STAGES - 1;
    uint32_t phF = 0, phE = 0;

    // -------- main loop: mbarrier-paced, no CTA barrier --------
    #pragma unroll 1
    for (int s = 0; s < KSTEPS; s++) {
        const uint32_t stg  = sb + SM_TILES + slotC * STG_BYTES;
        const uint32_t stgA = stg + OFF_A;
        const uint32_t stgB = stg + OFF_B;

        mbar_wait(mb_full + slotC * 8, (phF >> slotC) & 1);
        phF ^= 1u << slotC;

        // fragment double buffers; preload first kg (= kswap)
        uint32_t bf[2][8];
        uint32_t af[2][4];
        ldsm_x4(bf[0] + 0, stgB + swz64(b_row,      2 * kswap + b_ch));
        ldsm_x4(bf[0] + 4, stgB + swz64(b_row + 16, 2 * kswap + b_ch));
        ldsm_x4(af[0],     stgA + swz64(a_row,      2 * kswap + a_ch));

        // producer: refill slotP for stage s+4
        if (s + STAGES - 1 < KSTEPS) {
            if (s > 0) {
                mbar_wait(mb_empty + slotP * 8, (phE >> slotP) & 1);
                phE ^= 1u << slotP;
            }
            LOAD_STAGE(sb + SM_TILES + slotP * STG_BYTES, s + STAGES - 1);
            cp_mbar_arrive(mb_full + slotP * 8);
        }

        int ab = 0;
        #pragma unroll
        for (int kg = 0; kg < 2; kg++) {
            const int cur = kg;
            const int kk  = kg ^ kswap;
            const int kkn = kk ^ 1;             // the other kg
            if (kg < 1) {
                ldsm_x4(bf[1] + 0, stgB + swz64(b_row,      2 * kkn + b_ch));
                ldsm_x4(bf[1] + 4, stgB + swz64(b_row + 16, 2 * kkn + b_ch));
            }
            #pragma unroll
            for (int mt = 0; mt < 4; mt++) {
                if (mt < 3)
                    ldsm_x4(af[ab ^ 1], stgA + swz64(a_row + (mt + 1) * 16, 2 * kk + a_ch));
                else if (kg < 1)
                    ldsm_x4(af[ab ^ 1], stgA + swz64(a_row, 2 * kkn + a_ch));
                #pragma unroll
                for (int nt = 0; nt < 4; nt++)
                    mma_f16(acc[mt][nt], af[ab],
                            bf[cur][(nt >> 1) * 4 + (nt & 1) * 2],
                            bf[cur][(nt >> 1) * 4 + (nt & 1) * 2 + 1]);
                ab ^= 1;
            }
        }

        mbar_arrive(mb_empty + slotC * 8);

        slotC = (slotC == STAGES - 1) ? 0 : slotC + 1;
        slotP = (slotP == STAGES - 1) ? 0 : slotP + 1;
    }

    // -------- epilogue: y = xh + acc + bias; softsign --------
    const int r  = lane >> 2;
    const int cq = (lane & 3) * 2;
    const __half* xhp = g_xh + (size_t)bidx * TOK * DIMK;
    const float* bp  = bias + (size_t)day * DIMK;

    #pragma unroll
    for (int nt = 0; nt < 4; nt++) {
        const int n = n0 + nw + nt * 8 + cq;
        const float2 bb = *(const float2*)(bp + n);
        #pragma unroll
        for (int mt = 0; mt < 4; mt++) {
            const int m = m0 + mw + mt * 16 + r;
            const __half2 hx0 = *(const __half2*)(xhp + (size_t)m * DIMK + n);
            const __half2 hx1 = *(const __half2*)(xhp + (size_t)(m + 8) * DIMK + n);
            const float2 x0 = __half22float2(hx0);
            const float2 x1 = __half22float2(hx1);
            float y0 = acc[mt][nt][0] + x0.x + bb.x;
            float y1 = acc[mt][nt][1] + x0.y + bb.y;
            float y2 = acc[mt][nt][2] + x1.x + bb.x;
            float y3 = acc[mt][nt][3] + x1.y + bb.y;
            float2 o0, o1;
            o0.x = __fdividef(y0, 1.0f + fabsf(y0));
            o0.y = __fdividef(y1, 1.0f + fabsf(y1));
            o1.x = __fdividef(y2, 1.0f + fabsf(y2));
            o1.y = __fdividef(y3, 1.0f + fabsf(y3));
            *(float2*)(out + (size_t)bidx * TOK * DIMK + (size_t)m * DIMK + n)       = o0;
            *(float2*)(out + (size_t)bidx * TOK * DIMK + (size_t)(m + 8) * DIMK + n) = o1;
        }
    }
}

// ---------------- launch ----------------
extern "C" void kernel_launch(void* const* d_in, const int* in_sizes, int n_in,
                              void* d_out, int out_size)
{
    const float* x   = (const float*)d_in[0];
    const int*   day = (const int*)  d_in[1];
    const float* W   = (const float*)d_in[2];
    const float* b   = (const float*)d_in[3];
    float*       out = (float*)d_out;

    cudaFuncSetAttribute(day_adapter_f16,
                         cudaFuncAttributeMaxDynamicSharedMemorySize, SMEM_TOTAL);

    prep_fused<<<PREP_BLOCKS, 256>>>(x, W);

    dim3 grid(DIMK / CTA_N, TOK / CTA_M, NB);   // (4, 8, 64) = 2048 CTAs
    day_adapter_f16<<<grid, NTHREADS, SMEM_TOTAL>>>(x, day, b, out);
}

// round 16
// speedup vs baseline: 1.0686x; 1.0004x over previous
#include <cuda_runtime.h>
#include <cuda_fp16.h>
#include <stdint.h>

// DayAdapter via fp16 mma.sync m16n8k16: y = softsign(x + xh@Eh + b),
// E = W - I. Fused streaming prep (x->fp16 + E transpose in one launch).
// Main: R13 config (BK=32, 4-stage 16KB mbarrier cp.async pipeline, 2 CTAs/SM,
// warp tile 64x32, fp32-x epilogue) + L2 prefetch of the epilogue x tile
// issued 3 stages before the mainloop ends.

#define DIMK 512
#define TOK  1024
#define NB   64
#define NDAYS 24

#define CTA_M 128
#define CTA_N 128
#define BK    32
#define KSTEPS (DIMK / BK)       // 16
#define NTHREADS 256             // 8 warps: 2(m) x 4(n), warp tile 64x32
#define STAGES 4

#define SM_TILES 128             // mbarriers live in [0,128)
#define STG_BYTES 16384          // A 8KB | B 8KB, fp16 rows of 64B = 4 x 16B chunks
#define OFF_A 0
#define OFF_B 8192
#define SMEM_TOTAL (SM_TILES + STAGES * STG_BYTES)   // 65664

// prep grid split
#define XBLOCKS 16384            // 64*1024*512 / (8 floats/thread * 256 threads)
#define EBLOCKS 6144             // 24 days * 16*16 tiles of 32x32
#define PREP_BLOCKS (XBLOCKS + EBLOCKS)

__device__ __half g_xh[(size_t)NB * TOK * DIMK];       // fp16(x)
__device__ __half g_Eh[(size_t)NDAYS * DIMK * DIMK];   // fp16(E^T) [day][n][k]

// ---------------- helpers ----------------
__device__ __forceinline__ uint32_t smem_u32(const void* p) {
    return (uint32_t)__cvta_generic_to_shared(p);
}
// 64B rows, 4 chunks of 16B; conflict-free: ch ^= (row>>1)&3
__device__ __forceinline__ uint32_t swz64(uint32_t row, uint32_t ch) {
    return row * 64u + ((ch ^ ((row >> 1) & 3u)) << 4);
}
__device__ __forceinline__ void ldsm_x4(uint32_t* r, uint32_t addr) {
    asm volatile("ldmatrix.sync.aligned.m8n8.x4.shared.b16 {%0,%1,%2,%3}, [%4];"
                 : "=r"(r[0]), "=r"(r[1]), "=r"(r[2]), "=r"(r[3]) : "r"(addr));
}
__device__ __forceinline__ void mma_f16(float* c, const uint32_t* a, uint32_t b0, uint32_t b1) {
    asm volatile(
        "mma.sync.aligned.m16n8k16.row.col.f32.f16.f16.f32 "
        "{%0,%1,%2,%3}, {%4,%5,%6,%7}, {%8,%9}, {%0,%1,%2,%3};"
        : "+f"(c[0]), "+f"(c[1]), "+f"(c[2]), "+f"(c[3])
        : "r"(a[0]), "r"(a[1]), "r"(a[2]), "r"(a[3]), "r"(b0), "r"(b1));
}
__device__ __forceinline__ void cp_async16(uint32_t dst, const void* src) {
    asm volatile("cp.async.cg.shared.global [%0], [%1], 16;" :: "r"(dst), "l"(src));
}
__device__ __forceinline__ void cp_mbar_arrive(uint32_t mbar) {
    asm volatile("cp.async.mbarrier.arrive.noinc.shared.b64 [%0];" :: "r"(mbar) : "memory");
}
__device__ __forceinline__ void mbar_init(uint32_t addr, uint32_t cnt) {
    asm volatile("mbarrier.init.shared.b64 [%0], %1;" :: "r"(addr), "r"(cnt) : "memory");
}
__device__ __forceinline__ void mbar_arrive(uint32_t addr) {
    asm volatile("mbarrier.arrive.shared.b64 _, [%0];" :: "r"(addr) : "memory");
}
__device__ __forceinline__ void mbar_wait(uint32_t addr, uint32_t parity) {
    asm volatile(
        "{\n\t.reg .pred P;\n"
        "W%=:\n\t"
        "mbarrier.try_wait.parity.acquire.cta.shared::cta.b64 P, [%0], %1, 0x989680;\n\t"
        "@!P bra W%=;\n\t}"
        :: "r"(addr), "r"(parity) : "memory");
}
__device__ __forceinline__ void prefetch_l2(const void* p) {
    asm volatile("prefetch.global.L2 [%0];" :: "l"(p));
}

// ---------------- fused prep: x-convert + E-transpose in one launch ----------------
__global__ void __launch_bounds__(256, 8) prep_fused(const float* __restrict__ x,
                                                     const float* __restrict__ W)
{
    __shared__ float t[32][33];
    const int bid = blockIdx.x;
    if (bid < XBLOCKS) {
        const size_t i = (size_t)bid * 256 + threadIdx.x;   // uint4-of-half index
        const float4 v0 = __ldg((const float4*)x + 2 * i);
        const float4 v1 = __ldg((const float4*)x + 2 * i + 1);
        __half2 h0 = __float22half2_rn(make_float2(v0.x, v0.y));
        __half2 h1 = __float22half2_rn(make_float2(v0.z, v0.w));
        __half2 h2 = __float22half2_rn(make_float2(v1.x, v1.y));
        __half2 h3 = __float22half2_rn(make_float2(v1.z, v1.w));
        uint4 o;
        o.x = *(uint32_t*)&h0; o.y = *(uint32_t*)&h1;
        o.z = *(uint32_t*)&h2; o.w = *(uint32_t*)&h3;
        ((uint4*)g_xh)[i] = o;
    } else {
        const int eb = bid - XBLOCKS;
        const int d  = eb >> 8;
        const int tl = eb & 255;
        const int k0 = (tl >> 4) * 32;
        const int n0 = (tl & 15) * 32;
        const int tx = threadIdx.x & 31;
        const int ty = threadIdx.x >> 5;
        const float* Wd = W + (size_t)d * DIMK * DIMK;
        #pragma unroll
        for (int i = ty; i < 32; i += 8)
            t[i][tx] = Wd[(size_t)(k0 + i) * DIMK + n0 + tx];
        __syncthreads();
        #pragma unroll
        for (int i = ty; i < 32; i += 8) {
            const int k = k0 + tx;
            const int n = n0 + i;
            float v = t[tx][i] - ((k == n) ? 1.0f : 0.0f);
            g_Eh[((size_t)d * DIMK + n) * DIMK + k] = __float2half_rn(v);
        }
    }
}

// ---------------- main ----------------
__global__ void __launch_bounds__(NTHREADS, 2)
day_adapter_f16(const float* __restrict__ x,
                const int*   __restrict__ day_w,
                const float* __restrict__ bias,
                float*       __restrict__ out)
{
    extern __shared__ char smem[];
    const uint32_t sb = smem_u32(smem);
    const int tid  = threadIdx.x;
    const int wid  = tid >> 5;
    const int lane = tid & 31;

    const int n0   = blockIdx.x * CTA_N;
    const int m0   = blockIdx.y * CTA_M;
    const int bidx = blockIdx.z;

    const uint32_t mb_full  = sb;        // full[i] at sb + i*8
    const uint32_t mb_empty = sb + 64;   // empty[i] at sb + 64 + i*8
    if (tid == 0) {
        #pragma unroll
        for (int i = 0; i < STAGES; i++) {
            mbar_init(mb_full  + i * 8, NTHREADS);
            mbar_init(mb_empty + i * 8, NTHREADS);
        }
    }

    // robust day_ids decode (int32 vs int64 buffer)
    int is64 = 1;
    #pragma unroll 8
    for (int i = 1; i < 64; i += 2)
        if (__ldg(day_w + i) != 0) is64 = 0;
    const int day = is64 ? __ldg(day_w + 2 * bidx) : __ldg(day_w + bidx);

    __syncthreads();   // mbarrier init visible before any arrivals

    // -------- stage loaders: thread t -> row=t>>1, chunks (t&1)*2, +1 --------
    const int lrow = tid >> 1;
    const int lc0  = (tid & 1) * 2;
    const __half* agp = g_xh + ((size_t)bidx * TOK + m0 + lrow) * DIMK + lc0 * 8;
    const __half* bgp = g_Eh + ((size_t)day  * DIMK + n0 + lrow) * DIMK + lc0 * 8;
    const uint32_t lso0 = swz64(lrow, lc0), lso1 = swz64(lrow, lc0 + 1);

    auto LOAD_STAGE = [&](uint32_t stg, int s) {
        const __half* asrc = agp + s * BK;
        const __half* bsrc = bgp + s * BK;
        cp_async16(stg + OFF_A + lso0, asrc);
        cp_async16(stg + OFF_A + lso1, asrc + 8);
        cp_async16(stg + OFF_B + lso0, bsrc);
        cp_async16(stg + OFF_B + lso1, bsrc + 8);
    };

    // -------- warp tile: 2(m) x 4(n), 64x32 --------
    const int mw = (wid >> 2) * 64;
    const int nw = (wid & 3) * 32;
    const int kswap = wid & 1;               // odd warps traverse kg as 1,0

    float acc[4][4][4];
    #pragma unroll
    for (int i = 0; i < 4; i++)
        #pragma unroll
        for (int j = 0; j < 4; j++)
            #pragma unroll
            for (int q = 0; q < 4; q++) acc[i][j][q] = 0.0f;

    // ldmatrix lane addressing (fp16, 64B rows)
    const int a_row = mw + (lane & 15);                       // + mt*16
    const int a_ch  = lane >> 4;                              // + 2*kg
    const int b_row = nw + (lane & 7) + ((lane >> 4) << 3);   // + np*16
    const int b_ch  = (lane >> 3) & 1;                        // + 2*kg

    // epilogue x base (fp32), also used for mid-loop L2 prefetch
    const float* xep = x + (size_t)bidx * TOK * DIMK;

    // -------- prolog: fill slots 0..2 --------
    LOAD_STAGE(sb + SM_TILES + 0 * STG_BYTES, 0);
    cp_mbar_arrive(mb_full + 0 * 8);
    LOAD_STAGE(sb + SM_TILES + 1 * STG_BYTES, 1);
    cp_mbar_arrive(mb_full + 1 * 8);
    LOAD_STAGE(sb + SM_TILES + 2 * STG_BYTES, 2);
    cp_mbar_arrive(mb_full + 2 * 8);

    int slotC = 0;
    int slotP = STAGES - 1;
    uint32_t phF = 0, phE = 0;

    // -------- main loop: mbarrier-paced, no CTA barrier --------
    #pragma unroll 1
    for (int s = 0; s < KSTEPS; s++) {
        const uint32_t stg  = sb + SM_TILES + slotC * STG_BYTES;
        const uint32_t stgA = stg + OFF_A;
        const uint32_t stgB = stg + OFF_B;

        mbar_wait(mb_full + slotC * 8, (phF >> slotC) & 1);
        phF ^= 1u << slotC;

        // fragment double buffers; preload first kg (= kswap)
        uint32_t bf[2][8];
        uint32_t af[2][4];
        ldsm_x4(bf[0] + 0, stgB + swz64(b_row,      2 * kswap + b_ch));
        ldsm_x4(bf[0] + 4, stgB + swz64(b_row + 16, 2 * kswap + b_ch));
        ldsm_x4(af[0],     stgA + swz64(a_row,      2 * kswap + a_ch));

        // producer: refill slotP for stage s+3
        if (s + STAGES - 1 < KSTEPS) {
            if (s > 0) {
                mbar_wait(mb_empty + slotP * 8, (phE >> slotP) & 1);
                phE ^= 1u << slotP;
            }
            LOAD_STAGE(sb + SM_TILES + slotP * STG_BYTES, s + STAGES - 1);
            cp_mbar_arrive(mb_full + slotP * 8);
        }

        // L2-prefetch this CTA/warp's epilogue x tile (64 rows x 128B) well
        // before the tail: 2 lines per lane, ~3 stages of MMA work early.
        if (s == KSTEPS - 4) {
            prefetch_l2(xep + (size_t)(m0 + mw + lane) * DIMK + n0 + nw);
            prefetch_l2(xep + (size_t)(m0 + mw + 32 + lane) * DIMK + n0 + nw);
        }

        int ab = 0;
        #pragma unroll
        for (int kg = 0; kg < 2; kg++) {
            const int cur = kg;
            const int kk  = kg ^ kswap;
            const int kkn = kk ^ 1;             // the other kg
            if (kg < 1) {
                ldsm_x4(bf[1] + 0, stgB + swz64(b_row,      2 * kkn + b_ch));
                ldsm_x4(bf[1] + 4, stgB + swz64(b_row + 16, 2 * kkn + b_ch));
            }
            #pragma unroll
            for (int mt = 0; mt < 4; mt++) {
                if (mt < 3)
                    ldsm_x4(af[ab ^ 1], stgA + swz64(a_row + (mt + 1) * 16, 2 * kk + a_ch));
                else if (kg < 1)
                    ldsm_x4(af[ab ^ 1], stgA + swz64(a_row, 2 * kkn + a_ch));
                #pragma unroll
                for (int nt = 0; nt < 4; nt++)
                    mma_f16(acc[mt][nt], af[ab],
                            bf[cur][(nt >> 1) * 4 + (nt & 1) * 2],
                            bf[cur][(nt >> 1) * 4 + (nt & 1) * 2 + 1]);
                ab ^= 1;
            }
        }

        mbar_arrive(mb_empty + slotC * 8);

        slotC = (slotC == STAGES - 1) ? 0 : slotC + 1;
        slotP = (slotP == STAGES - 1) ? 0 : slotP + 1;
    }

    // -------- epilogue: y = x (exact fp32) + acc + bias; softsign --------
    const int r  = lane >> 2;
    const int cq = (lane & 3) * 2;
    const float* bp  = bias + (size_t)day * DIMK;

    #pragma unroll
    for (int nt = 0; nt < 4; nt++) {
        const int n = n0 + nw + nt * 8 + cq;
        const float2 bb = *(const float2*)(bp + n);
        #pragma unroll
        for (int mt = 0; mt < 4; mt++) {
            const int m = m0 + mw + mt * 16 + r;
            const float2 x0 = __ldg((const float2*)(xep + (size_t)m * DIMK + n));
            const float2 x1 = __ldg((const float2*)(xep + (size_t)(m + 8) * DIMK + n));
            float y0 = acc[mt][nt][0] + x0.x + bb.x;
            float y1 = acc[mt][nt][1] + x0.y + bb.y;
            float y2 = acc[mt][nt][2] + x1.x + bb.x;
            float y3 = acc[mt][nt][3] + x1.y + bb.y;
            float2 o0, o1;
            o0.x = __fdividef(y0, 1.0f + fabsf(y0));
            o0.y = __fdividef(y1, 1.0f + fabsf(y1));
            o1.x = __fdividef(y2, 1.0f + fabsf(y2));
            o1.y = __fdividef(y3, 1.0f + fabsf(y3));
            *(float2*)(out + (size_t)bidx * TOK * DIMK + (size_t)m * DIMK + n)       = o0;
            *(float2*)(out + (size_t)bidx * TOK * DIMK + (size_t)(m + 8) * DIMK + n) = o1;
        }
    }
}

// ---------------- launch ----------------
extern "C" void kernel_launch(void* const* d_in, const int* in_sizes, int n_in,
                              void* d_out, int out_size)
{
    const float* x   = (const float*)d_in[0];
    const int*   day = (const int*)  d_in[1];
    const float* W   = (const float*)d_in[2];
    const float* b   = (const float*)d_in[3];
    float*       out = (float*)d_out;

    cudaFuncSetAttribute(day_adapter_f16,
                         cudaFuncAttributeMaxDynamicSharedMemorySize, SMEM_TOTAL);

    prep_fused<<<PREP_BLOCKS, 256>>>(x, W);

    dim3 grid(DIMK / CTA_N, TOK / CTA_M, NB);   // (4, 8, 64) = 2048 CTAs
    day_adapter_f16<<<grid, NTHREADS, SMEM_TOTAL>>>(x, day, b, out);
}

// round 17
// speedup vs baseline: 1.0970x; 1.0266x over previous
#include <cuda_runtime.h>
#include <cuda_fp16.h>
#include <stdint.h>

// DayAdapter via fp16 mma.sync m16n8k16: y = softsign(x + xh@Eh + b),
// E = W - I. Fused streaming prep (x->fp16 + E transpose overlap in one
// launch). Main: BK=32, 4-stage (16KB/stage) mbarrier cp.async pipeline,
// 2 CTAs/SM, warp tile 64x32, exact-fp32 identity term in epilogue.
// (R13 champion configuration, locked in.)

#define DIMK 512
#define TOK  1024
#define NB   64
#define NDAYS 24

#define CTA_M 128
#define CTA_N 128
#define BK    32
#define KSTEPS (DIMK / BK)       // 16
#define NTHREADS 256             // 8 warps: 2(m) x 4(n), warp tile 64x32
#define STAGES 4

#define SM_TILES 128             // mbarriers live in [0,128)
#define STG_BYTES 16384          // A 8KB | B 8KB, fp16 rows of 64B = 4 x 16B chunks
#define OFF_A 0
#define OFF_B 8192
#define SMEM_TOTAL (SM_TILES + STAGES * STG_BYTES)   // 65664

// prep grid split
#define XBLOCKS 16384            // 64*1024*512 / (8 floats/thread * 256 threads)
#define EBLOCKS 6144             // 24 days * 16*16 tiles of 32x32
#define PREP_BLOCKS (XBLOCKS + EBLOCKS)

__device__ __half g_xh[(size_t)NB * TOK * DIMK];       // fp16(x)
__device__ __half g_Eh[(size_t)NDAYS * DIMK * DIMK];   // fp16(E^T) [day][n][k]

// ---------------- helpers ----------------
__device__ __forceinline__ uint32_t smem_u32(const void* p) {
    return (uint32_t)__cvta_generic_to_shared(p);
}
// 64B rows, 4 chunks of 16B; conflict-free: ch ^= (row>>1)&3
__device__ __forceinline__ uint32_t swz64(uint32_t row, uint32_t ch) {
    return row * 64u + ((ch ^ ((row >> 1) & 3u)) << 4);
}
__device__ __forceinline__ void ldsm_x4(uint32_t* r, uint32_t addr) {
    asm volatile("ldmatrix.sync.aligned.m8n8.x4.shared.b16 {%0,%1,%2,%3}, [%4];"
                 : "=r"(r[0]), "=r"(r[1]), "=r"(r[2]), "=r"(r[3]) : "r"(addr));
}
__device__ __forceinline__ void mma_f16(float* c, const uint32_t* a, uint32_t b0, uint32_t b1) {
    asm volatile(
        "mma.sync.aligned.m16n8k16.row.col.f32.f16.f16.f32 "
        "{%0,%1,%2,%3}, {%4,%5,%6,%7}, {%8,%9}, {%0,%1,%2,%3};"
        : "+f"(c[0]), "+f"(c[1]), "+f"(c[2]), "+f"(c[3])
        : "r"(a[0]), "r"(a[1]), "r"(a[2]), "r"(a[3]), "r"(b0), "r"(b1));
}
__device__ __forceinline__ void cp_async16(uint32_t dst, const void* src) {
    asm volatile("cp.async.cg.shared.global [%0], [%1], 16;" :: "r"(dst), "l"(src));
}
__device__ __forceinline__ void cp_mbar_arrive(uint32_t mbar) {
    asm volatile("cp.async.mbarrier.arrive.noinc.shared.b64 [%0];" :: "r"(mbar) : "memory");
}
__device__ __forceinline__ void mbar_init(uint32_t addr, uint32_t cnt) {
    asm volatile("mbarrier.init.shared.b64 [%0], %1;" :: "r"(addr), "r"(cnt) : "memory");
}
__device__ __forceinline__ void mbar_arrive(uint32_t addr) {
    asm volatile("mbarrier.arrive.shared.b64 _, [%0];" :: "r"(addr) : "memory");
}
__device__ __forceinline__ void mbar_wait(uint32_t addr, uint32_t parity) {
    asm volatile(
        "{\n\t.reg .pred P;\n"
        "W%=:\n\t"
        "mbarrier.try_wait.parity.acquire.cta.shared::cta.b64 P, [%0], %1, 0x989680;\n\t"
        "@!P bra W%=;\n\t}"
        :: "r"(addr), "r"(parity) : "memory");
}

// ---------------- fused prep: x-convert + E-transpose in one launch ----------------
__global__ void __launch_bounds__(256, 8) prep_fused(const float* __restrict__ x,
                                                     const float* __restrict__ W)
{
    __shared__ float t[32][33];
    const int bid = blockIdx.x;
    if (bid < XBLOCKS) {
        const size_t i = (size_t)bid * 256 + threadIdx.x;   // uint4-of-half index
        const float4 v0 = __ldg((const float4*)x + 2 * i);
        const float4 v1 = __ldg((const float4*)x + 2 * i + 1);
        __half2 h0 = __float22half2_rn(make_float2(v0.x, v0.y));
        __half2 h1 = __float22half2_rn(make_float2(v0.z, v0.w));
        __half2 h2 = __float22half2_rn(make_float2(v1.x, v1.y));
        __half2 h3 = __float22half2_rn(make_float2(v1.z, v1.w));
        uint4 o;
        o.x = *(uint32_t*)&h0; o.y = *(uint32_t*)&h1;
        o.z = *(uint32_t*)&h2; o.w = *(uint32_t*)&h3;
        ((uint4*)g_xh)[i] = o;
    } else {
        const int eb = bid - XBLOCKS;
        const int d  = eb >> 8;
        const int tl = eb & 255;
        const int k0 = (tl >> 4) * 32;
        const int n0 = (tl & 15) * 32;
        const int tx = threadIdx.x & 31;
        const int ty = threadIdx.x >> 5;
        const float* Wd = W + (size_t)d * DIMK * DIMK;
        #pragma unroll
        for (int i = ty; i < 32; i += 8)
            t[i][tx] = Wd[(size_t)(k0 + i) * DIMK + n0 + tx];
        __syncthreads();
        #pragma unroll
        for (int i = ty; i < 32; i += 8) {
            const int k = k0 + tx;
            const int n = n0 + i;
            float v = t[tx][i] - ((k == n) ? 1.0f : 0.0f);
            g_Eh[((size_t)d * DIMK + n) * DIMK + k] = __float2half_rn(v);
        }
    }
}

// ---------------- main ----------------
__global__ void __launch_bounds__(NTHREADS, 2)
day_adapter_f16(const float* __restrict__ x,
                const int*   __restrict__ day_w,
                const float* __restrict__ bias,
                float*       __restrict__ out)
{
    extern __shared__ char smem[];
    const uint32_t sb = smem_u32(smem);
    const int tid  = threadIdx.x;
    const int wid  = tid >> 5;
    const int lane = tid & 31;

    const int n0   = blockIdx.x * CTA_N;
    const int m0   = blockIdx.y * CTA_M;
    const int bidx = blockIdx.z;

    const uint32_t mb_full  = sb;        // full[i] at sb + i*8
    const uint32_t mb_empty = sb + 64;   // empty[i] at sb + 64 + i*8
    if (tid == 0) {
        #pragma unroll
        for (int i = 0; i < STAGES; i++) {
            mbar_init(mb_full  + i * 8, NTHREADS);
            mbar_init(mb_empty + i * 8, NTHREADS);
        }
    }

    // robust day_ids decode (int32 vs int64 buffer)
    int is64 = 1;
    #pragma unroll 8
    for (int i = 1; i < 64; i += 2)
        if (__ldg(day_w + i) != 0) is64 = 0;
    const int day = is64 ? __ldg(day_w + 2 * bidx) : __ldg(day_w + bidx);

    __syncthreads();   // mbarrier init visible before any arrivals

    // -------- stage loaders: thread t -> row=t>>1, chunks (t&1)*2, +1 --------
    const int lrow = tid >> 1;
    const int lc0  = (tid & 1) * 2;
    const __half* agp = g_xh + ((size_t)bidx * TOK + m0 + lrow) * DIMK + lc0 * 8;
    const __half* bgp = g_Eh + ((size_t)day  * DIMK + n0 + lrow) * DIMK + lc0 * 8;
    const uint32_t lso0 = swz64(lrow, lc0), lso1 = swz64(lrow, lc0 + 1);

    auto LOAD_STAGE = [&](uint32_t stg, int s) {
        const __half* asrc = agp + s * BK;
        const __half* bsrc = bgp + s * BK;
        cp_async16(stg + OFF_A + lso0, asrc);
        cp_async16(stg + OFF_A + lso1, asrc + 8);
        cp_async16(stg + OFF_B + lso0, bsrc);
        cp_async16(stg + OFF_B + lso1, bsrc + 8);
    };

    // -------- warp tile: 2(m) x 4(n), 64x32 --------
    const int mw = (wid >> 2) * 64;
    const int nw = (wid & 3) * 32;
    const int kswap = wid & 1;               // odd warps traverse kg as 1,0

    float acc[4][4][4];
    #pragma unroll
    for (int i = 0; i < 4; i++)
        #pragma unroll
        for (int j = 0; j < 4; j++)
            #pragma unroll
            for (int q = 0; q < 4; q++) acc[i][j][q] = 0.0f;

    // ldmatrix lane addressing (fp16, 64B rows)
    const int a_row = mw + (lane & 15);                       // + mt*16
    const int a_ch  = lane >> 4;                              // + 2*kg
    const int b_row = nw + (lane & 7) + ((lane >> 4) << 3);   // + np*16
    const int b_ch  = (lane >> 3) & 1;                        // + 2*kg

    // -------- prolog: fill slots 0..2 --------
    LOAD_STAGE(sb + SM_TILES + 0 * STG_BYTES, 0);
    cp_mbar_arrive(mb_full + 0 * 8);
    LOAD_STAGE(sb + SM_TILES + 1 * STG_BYTES, 1);
    cp_mbar_arrive(mb_full + 1 * 8);
    LOAD_STAGE(sb + SM_TILES + 2 * STG_BYTES, 2);
    cp_mbar_arrive(mb_full + 2 * 8);

    int slotC = 0;
    int slotP = STAGES - 1;
    uint32_t phF = 0, phE = 0;

    // -------- main loop: mbarrier-paced, no CTA barrier --------
    #pragma unroll 1
    for (int s = 0; s < KSTEPS; s++) {
        const uint32_t stg  = sb + SM_TILES + slotC * STG_BYTES;
        const uint32_t stgA = stg + OFF_A;
        const uint32_t stgB = stg + OFF_B;

        mbar_wait(mb_full + slotC * 8, (phF >> slotC) & 1);
        phF ^= 1u << slotC;

        // fragment double buffers; preload first kg (= kswap)
        uint32_t bf[2][8];
        uint32_t af[2][4];
        ldsm_x4(bf[0] + 0, stgB + swz64(b_row,      2 * kswap + b_ch));
        ldsm_x4(bf[0] + 4, stgB + swz64(b_row + 16, 2 * kswap + b_ch));
        ldsm_x4(af[0],     stgA + swz64(a_row,      2 * kswap + a_ch));

        // producer: refill slotP for stage s+3
        if (s + STAGES - 1 < KSTEPS) {
            if (s > 0) {
                mbar_wait(mb_empty + slotP * 8, (phE >> slotP) & 1);
                phE ^= 1u << slotP;
            }
            LOAD_STAGE(sb + SM_TILES + slotP * STG_BYTES, s + STAGES - 1);
            cp_mbar_arrive(mb_full + slotP * 8);
        }

        int ab = 0;
        #pragma unroll
        for (int kg = 0; kg < 2; kg++) {
            const int cur = kg;
            const int kk  = kg ^ kswap;
            const int kkn = kk ^ 1;             // the other kg
            if (kg < 1) {
                ldsm_x4(bf[1] + 0, stgB + swz64(b_row,      2 * kkn + b_ch));
                ldsm_x4(bf[1] + 4, stgB + swz64(b_row + 16, 2 * kkn + b_ch));
            }
            #pragma unroll
            for (int mt = 0; mt < 4; mt++) {
                if (mt < 3)
                    ldsm_x4(af[ab ^ 1], stgA + swz64(a_row + (mt + 1) * 16, 2 * kk + a_ch));
                else if (kg < 1)
                    ldsm_x4(af[ab ^ 1], stgA + swz64(a_row, 2 * kkn + a_ch));
                #pragma unroll
                for (int nt = 0; nt < 4; nt++)
                    mma_f16(acc[mt][nt], af[ab],
                            bf[cur][(nt >> 1) * 4 + (nt & 1) * 2],
                            bf[cur][(nt >> 1) * 4 + (nt & 1) * 2 + 1]);
                ab ^= 1;
            }
        }

        mbar_arrive(mb_empty + slotC * 8);

        slotC = (slotC == STAGES - 1) ? 0 : slotC + 1;
        slotP = (slotP == STAGES - 1) ? 0 : slotP + 1;
    }

    // -------- epilogue: y = x (exact fp32) + acc + bias; softsign --------
    const int r  = lane >> 2;
    const int cq = (lane & 3) * 2;
    const float* xep = x + (size_t)bidx * TOK * DIMK;
    const float* bp  = bias + (size_t)day * DIMK;

    #pragma unroll
    for (int nt = 0; nt < 4; nt++) {
        const int n = n0 + nw + nt * 8 + cq;
        const float2 bb = *(const float2*)(bp + n);
        #pragma unroll
        for (int mt = 0; mt < 4; mt++) {
            const int m = m0 + mw + mt * 16 + r;
            const float2 x0 = __ldg((const float2*)(xep + (size_t)m * DIMK + n));
            const float2 x1 = __ldg((const float2*)(xep + (size_t)(m + 8) * DIMK + n));
            float y0 = acc[mt][nt][0] + x0.x + bb.x;
            float y1 = acc[mt][nt][1] + x0.y + bb.y;
            float y2 = acc[mt][nt][2] + x1.x + bb.x;
            float y3 = acc[mt][nt][3] + x1.y + bb.y;
            float2 o0, o1;
            o0.x = __fdividef(y0, 1.0f + fabsf(y0));
            o0.y = __fdividef(y1, 1.0f + fabsf(y1));
            o1.x = __fdividef(y2, 1.0f + fabsf(y2));
            o1.y = __fdividef(y3, 1.0f + fabsf(y3));
            *(float2*)(out + (size_t)bidx * TOK * DIMK + (size_t)m * DIMK + n)       = o0;
            *(float2*)(out + (size_t)bidx * TOK * DIMK + (size_t)(m + 8) * DIMK + n) = o1;
        }
    }
}

// ---------------- launch ----------------
extern "C" void kernel_launch(void* const* d_in, const int* in_sizes, int n_in,
                              void* d_out, int out_size)
{
    const float* x   = (const float*)d_in[0];
    const int*   day = (const int*)  d_in[1];
    const float* W   = (const float*)d_in[2];
    const float* b   = (const float*)d_in[3];
    float*       out = (float*)d_out;

    cudaFuncSetAttribute(day_adapter_f16,
                         cudaFuncAttributeMaxDynamicSharedMemorySize, SMEM_TOTAL);

    prep_fused<<<PREP_BLOCKS, 256>>>(x, W);

    dim3 grid(DIMK / CTA_N, TOK / CTA_M, NB);   // (4, 8, 64) = 2048 CTAs
    day_adapter_f16<<<grid, NTHREADS, SMEM_TOTAL>>>(x, day, b, out);
}